// round 8
// baseline (speedup 1.0000x reference)
#include <cuda_runtime.h>
#include <cstdint>

#define B_N   8
#define CIN   64
#define CATT  32
#define BD    5
#define H     128
#define W     128
#define HW    (H*W)            /* 16384 */
#define CH_STRIDE (BD*HW)      /* 81920 */
#define TY 16
#define TW 64
#define TS 72                  /* tile row stride (floats) */

typedef unsigned long long ull;

// scratch for q, k, v : 8*32*5*128*128 floats each (83.9 MB)
__device__ __align__(128) float g_q[(size_t)B_N*CATT*BD*HW];
__device__ __align__(128) float g_k[(size_t)B_N*CATT*BD*HW];
__device__ __align__(128) float g_v[(size_t)B_N*CATT*BD*HW];

// ---- f32x2 helpers ----
__device__ __forceinline__ ull pk(float lo, float hi) {
    ull r;
    asm("mov.b64 %0, {%1, %2};" : "=l"(r) : "f"(lo), "f"(hi));
    return r;
}
__device__ __forceinline__ void fma2(ull& d, ull a, ull b) {
    asm("fma.rn.f32x2 %0, %1, %2, %0;" : "+l"(d) : "l"(a), "l"(b));
}
__device__ __forceinline__ float2 u2f(ull u) {
    float2 f;
    asm("mov.b64 {%0, %1}, %2;" : "=f"(f.x), "=f"(f.y) : "l"(u));
    return f;
}
__device__ __forceinline__ float lo32(ull u) {
    float f; asm("{ .reg .f32 t; mov.b64 {%0, t}, %1; }" : "=f"(f) : "l"(u));
    return f;
}
__device__ __forceinline__ float hi32(ull u) {
    float f; asm("{ .reg .f32 t; mov.b64 {t, %0}, %1; }" : "=f"(f) : "l"(u));
    return f;
}

// ============================================================================
// Grouped 3x3x3 conv, groups=32 (2 in-ch per out-ch), one output tensor
// selected by SEL (0 = g_q, 1 = g_k, 2 = g_v) — resolved in DEVICE code
// (passing a __device__ symbol from host is invalid and was the R6/R7 bug).
// Block: 128 threads = 8 x-threads (8 outputs each) x 16 y-threads.
// The 2 input channels (din) are processed in two sequential phases sharing
// one tile buffer [5][18][72] (25.9 KB static smem).
// XOR column swizzle (bit5 -> bit2) keeps all LDS.128/LDS.64 row reads
// bank-conflict-free.
// ============================================================================
template<int SEL>
__global__ __launch_bounds__(128, 4)
void conv3d_tx8(const float* __restrict__ in,
                const float* __restrict__ wgt,
                float wscale)
{
    float* const out = (SEL == 0) ? g_q : (SEL == 1) ? g_k : g_v;

    __shared__ float  tile[BD][TY+2][TS];
    __shared__ float2 wsp[54];       // (w,w) broadcast pairs

    const int tid = threadIdx.x;
    const int c   = blockIdx.z & 31;
    const int bb  = blockIdx.z >> 5;
    const int y0  = blockIdx.y * TY;
    const int x0  = blockIdx.x * TW;

    if (tid < 54) {
        float a = wgt[c*54 + tid] * wscale;
        wsp[tid] = make_float2(a, a);
    }

    // loader thread mapping (computed once)
    const int lx = tid & 63;       // 0..63
    const int wg = tid >> 6;       // 0..1 : rows wg*9 .. wg*9+8
    const int gx  = x0 - 1 + lx;
    const bool okx  = (unsigned)gx < (unsigned)W;
    const bool halo = (lx < 2);
    const int gx2 = gx + 64;
    const bool okx2 = halo && ((unsigned)gx2 < (unsigned)W);
    const int cs  = lx ^ ((lx & 32) >> 3);   // swizzled col
    const int cs2 = lx + 64;                 // cols 64,65: bit5=0, no swizzle
    const int yyb = wg * 9;
    const int gyb = y0 - 1 + yyb;

    bool oky[9];
    #pragma unroll
    for (int t = 0; t < 9; ++t)
        oky[t] = (unsigned)(gyb + t) < (unsigned)H;

    const float* inb = in + ((size_t)(bb*CIN + 2*c))*CH_STRIDE
                          + (ptrdiff_t)gyb * W;

    // compute thread mapping
    const int tx = tid & 7;          // 8 x-threads, 8 outputs each
    const int ty = tid >> 3;         // 16 y rows
    const int cb = tx * 8;
    const int o1 =  cb      ^ (( cb       & 32) >> 3);
    const int o2 = (cb + 4) ^ (((cb + 4)  & 32) >> 3);
    const int o3 = (cb + 8) ^ (((cb + 8)  & 32) >> 3);

    ull acc[BD][4];
    #pragma unroll
    for (int bo = 0; bo < BD; ++bo)
        #pragma unroll
        for (int j = 0; j < 4; ++j) acc[bo][j] = 0ull;

    #pragma unroll
    for (int din = 0; din < 2; ++din) {
        if (din) __syncthreads();    // prior phase's reads must finish

        // ---- load this input channel's tile ----
        {
            const float* srcb = inb + din*BD*HW;
            #pragma unroll
            for (int Bi = 0; Bi < BD; ++Bi) {
                const float* src = srcb + Bi*HW;
                float* dst = &tile[Bi][yyb][0];
                #pragma unroll
                for (int t = 0; t < 9; ++t) {
                    float v = (oky[t] & okx) ? src[t*W + gx] : 0.f;
                    dst[t*TS + cs] = v;
                }
                if (halo) {
                    #pragma unroll
                    for (int t = 0; t < 9; ++t) {
                        float v2 = (oky[t] & okx2) ? src[t*W + gx2] : 0.f;
                        dst[t*TS + cs2] = v2;
                    }
                }
            }
        }
        __syncthreads();

        // ---- accumulate ----
        #pragma unroll
        for (int dy = 0; dy < 3; ++dy) {
            ull wr2[9];
            #pragma unroll
            for (int dB = 0; dB < 3; ++dB)
                #pragma unroll
                for (int dx = 0; dx < 3; ++dx)
                    wr2[dB*3+dx] = *(const ull*)&wsp[din*27 + dB*9 + dy*3 + dx];

            #pragma unroll
            for (int Bi = 0; Bi < BD; ++Bi) {
                const float* rowp = &tile[Bi][ty + dy][0];
                ulonglong2 Aa = *(const ulonglong2*)(rowp + o1); // (x0,x1),(x2,x3)
                ulonglong2 Bb = *(const ulonglong2*)(rowp + o2); // (x4,x5),(x6,x7)
                ull        E4 = *(const ull*)(rowp + o3);        // (x8,x9)
                ull E[5] = { Aa.x, Aa.y, Bb.x, Bb.y, E4 };
                ull C[4];
                #pragma unroll
                for (int j = 0; j < 4; ++j)
                    C[j] = pk(hi32(E[j]), lo32(E[j+1]));

                #pragma unroll
                for (int dB = 0; dB < 3; ++dB) {
                    const int Bo = Bi + 1 - dB;
                    if (Bo < 0 || Bo >= BD) continue;
                    #pragma unroll
                    for (int j = 0; j < 4; ++j) {
                        fma2(acc[Bo][j], E[j],   wr2[dB*3+0]);
                        fma2(acc[Bo][j], C[j],   wr2[dB*3+1]);
                        fma2(acc[Bo][j], E[j+1], wr2[dB*3+2]);
                    }
                }
            }
        }
    }

    const size_t ob = ((size_t)(bb*CATT + c))*CH_STRIDE
                    + (size_t)(y0 + ty)*W + x0 + cb;
    #pragma unroll
    for (int Bo = 0; Bo < BD; ++Bo) {
        float2 a0 = u2f(acc[Bo][0]);
        float2 a1 = u2f(acc[Bo][1]);
        float2 a2 = u2f(acc[Bo][2]);
        float2 a3 = u2f(acc[Bo][3]);
        float* op = out + ob + (size_t)Bo*HW;
        *(float4*)(op)     = make_float4(a0.x, a0.y, a1.x, a1.y);
        *(float4*)(op + 4) = make_float4(a2.x, a2.y, a3.x, a3.y);
    }
}

// ============================================================================
// Attention (over B=5, 8 heads, head_dim=4) + grouped 1x1x1 projection.
// q is pre-scaled (SCALE folded into wq at conv time).
// ============================================================================
__global__ __launch_bounds__(256)
void attn_proj_kernel(const float* __restrict__ wproj, float* __restrict__ out)
{
    __shared__ float wp[64];
    if (threadIdx.x < 64) wp[threadIdx.x] = wproj[threadIdx.x];
    __syncthreads();

    const int p = blockIdx.x * 256 + threadIdx.x;
    if (p >= B_N * HW) return;
    const int bb = p >> 14;
    const int yx = p & (HW - 1);
    const size_t base = (size_t)bb * CATT * CH_STRIDE + yx;

    #pragma unroll 1
    for (int hd = 0; hd < 8; ++hd) {
        float q[BD][4], k[BD][4], v[BD][4];
        #pragma unroll
        for (int d = 0; d < 4; ++d) {
            const size_t cb = base + (size_t)(hd*4 + d) * CH_STRIDE;
            #pragma unroll
            for (int Bi = 0; Bi < BD; ++Bi) {
                q[Bi][d] = g_q[cb + Bi*HW];
                k[Bi][d] = g_k[cb + Bi*HW];
                v[Bi][d] = g_v[cb + Bi*HW];
            }
        }
        #pragma unroll
        for (int i = 0; i < BD; ++i) {
            float s[BD];
            #pragma unroll
            for (int j = 0; j < BD; ++j) {
                float t = q[i][0] * k[j][0];
                t = fmaf(q[i][1], k[j][1], t);
                t = fmaf(q[i][2], k[j][2], t);
                t = fmaf(q[i][3], k[j][3], t);
                s[j] = t;
            }
            float m = s[0];
            #pragma unroll
            for (int j = 1; j < BD; ++j) m = fmaxf(m, s[j]);
            float e[BD], sum = 0.f;
            #pragma unroll
            for (int j = 0; j < BD; ++j) { e[j] = __expf(s[j] - m); sum += e[j]; }
            const float inv = 1.0f / sum;
            #pragma unroll
            for (int d = 0; d < 4; ++d) {
                float t = e[0] * v[0][d];
                #pragma unroll
                for (int j = 1; j < BD; ++j) t = fmaf(e[j], v[j][d], t);
                const float od = t * inv;
                const int ch = hd*4 + d;
                const size_t obx = ((size_t)(bb*CIN + 2*ch)*BD + i)*HW + yx;
                out[obx]                 = od * wp[2*ch];
                out[obx + (size_t)BD*HW] = od * wp[2*ch + 1];
            }
        }
    }
}

extern "C" void kernel_launch(void* const* d_in, const int* in_sizes, int n_in,
                              void* d_out, int out_size) {
    const float* x     = (const float*)d_in[0];
    const float* last  = (const float*)d_in[1];
    const float* wq    = (const float*)d_in[2];
    const float* wk    = (const float*)d_in[3];
    const float* wv    = (const float*)d_in[4];
    const float* wproj = (const float*)d_in[5];
    float* out = (float*)d_out;

    const float SCALE = 0.35355339059327373f;   // 8^{-1/2}

    dim3 cgrid(W/TW, H/TY, B_N*CATT);   // (2, 8, 256)
    conv3d_tx8<0><<<cgrid, 128>>>(x,    wq, SCALE);
    conv3d_tx8<1><<<cgrid, 128>>>(last, wk, 1.0f);
    conv3d_tx8<2><<<cgrid, 128>>>(last, wv, 1.0f);
    attn_proj_kernel<<<(B_N*HW + 255)/256, 256>>>(wproj, out);
}